// round 5
// baseline (speedup 1.0000x reference)
#include <cuda_runtime.h>
#include <math.h>

#define N_NODES 50000
#define N_EDGES 800000
#define EMB     100
#define NF4     25          // float4 per row
#define SCAN_B  256
#define SCAN_NB ((N_NODES + SCAN_B - 1) / SCAN_B)   // 196

// ---- static scratch (allocation-free rule: __device__ globals) ----
__device__ int   g_rowoff[N_NODES + 1];   // CSR row offsets
__device__ int   g_cursor[N_NODES];       // counts -> scatter cursors
__device__ int   g_flag[SCAN_NB];         // lookback: (sum<<2)|state, 0=empty,1=agg,2=prefix
__device__ int2  g_edges[N_EDGES];        // packed {col*EMB, val bits}, grouped by row
__device__ float g_x1[N_NODES * EMB];
__device__ float g_x2[N_NODES * EMB];

// ---------------- CSR build ----------------
__global__ void hist_kernel(const int* __restrict__ row) {
    int e = blockIdx.x * blockDim.x + threadIdx.x;
    if (e < N_EDGES) atomicAdd(&g_cursor[row[e]], 1);
}

// single-pass scan with decoupled lookback:
// counts (g_cursor) -> rowoff[i+1] inclusive, cursor[i] exclusive start.
__global__ void __launch_bounds__(SCAN_B) scan_lookback_kernel() {
    __shared__ int wsum[8];
    __shared__ int s_total;
    __shared__ int s_prefix;
    const int bid  = blockIdx.x;
    const int t    = threadIdx.x;
    const int lane = t & 31, warp = t >> 5;
    const int i    = bid * SCAN_B + t;

    int v = (i < N_NODES) ? g_cursor[i] : 0;

    // block inclusive scan
    int x = v;
    #pragma unroll
    for (int off = 1; off < 32; off <<= 1) {
        int y = __shfl_up_sync(0xFFFFFFFFu, x, off);
        if (lane >= off) x += y;
    }
    if (lane == 31) wsum[warp] = x;
    __syncthreads();
    if (warp == 0) {
        int w = (lane < 8) ? wsum[lane] : 0;
        #pragma unroll
        for (int off = 1; off < 8; off <<= 1) {
            int y = __shfl_up_sync(0xFFFFFFFFu, w, off);
            if (lane >= off) w += y;
        }
        if (lane < 8) wsum[lane] = w;
    }
    __syncthreads();
    int incl = x + (warp > 0 ? wsum[warp - 1] : 0);
    if (t == SCAN_B - 1) s_total = incl;
    __syncthreads();
    const int total = s_total;

    // warp 0: publish + lookback
    if (warp == 0) {
        if (lane == 0)
            atomicExch(&g_flag[bid], (total << 2) | (bid == 0 ? 2 : 1));
        int prefix = 0;
        if (bid > 0) {
            int j = bid - 1;
            bool done = false;
            while (!done) {
                int idx = j - lane;
                int f;
                do {
                    f = (idx >= 0) ? atomicAdd(&g_flag[idx], 0) : 2;  // OOB = prefix 0
                } while (__any_sync(0xFFFFFFFFu, (f & 3) == 0));
                unsigned pm = __ballot_sync(0xFFFFFFFFu, (f & 3) == 2);
                int p = __ffs(pm) - 1;               // lowest lane with a full prefix
                int contrib = (p < 0 || lane <= p) ? (f >> 2) : 0;
                #pragma unroll
                for (int off = 16; off > 0; off >>= 1)
                    contrib += __shfl_xor_sync(0xFFFFFFFFu, contrib, off);
                prefix += contrib;
                if (p >= 0) done = true; else j -= 32;
            }
            if (lane == 0)
                atomicExch(&g_flag[bid], ((prefix + total) << 2) | 2);
        }
        if (lane == 0) s_prefix = prefix;
    }
    __syncthreads();

    int incl_g = incl + s_prefix;
    if (i < N_NODES) {
        g_rowoff[i + 1] = incl_g;
        g_cursor[i] = incl_g - v;    // exclusive start = scatter cursor
    }
    if (i == 0) g_rowoff[0] = 0;
}

__global__ void scatter_kernel(const int* __restrict__ row,
                               const int* __restrict__ col,
                               const float* __restrict__ val) {
    int e = blockIdx.x * blockDim.x + threadIdx.x;
    if (e < N_EDGES) {
        int pos = atomicAdd(&g_cursor[row[e]], 1);
        g_edges[pos] = make_int2(col[e] * EMB, __float_as_int(val[e]));
    }
}

// ---------------- SpMM: warp per row, uniform edge loads, float4 gathers ----------------
__device__ __forceinline__ float4 spmm_row(const float* __restrict__ x,
                                           int r, int lane) {
    const int s = __ldg(&g_rowoff[r]);
    const int e = __ldg(&g_rowoff[r + 1]);
    float4 acc = make_float4(0.f, 0.f, 0.f, 0.f);
    if (lane >= NF4) return acc;
    float4 acc2 = make_float4(0.f, 0.f, 0.f, 0.f);

    int k = s;
    for (; k + 4 <= e; k += 4) {
        int2 e0 = __ldg(&g_edges[k + 0]);
        int2 e1 = __ldg(&g_edges[k + 1]);
        int2 e2 = __ldg(&g_edges[k + 2]);
        int2 e3 = __ldg(&g_edges[k + 3]);
        float4 x0 = __ldg((const float4*)(x + e0.x) + lane);
        float4 x1 = __ldg((const float4*)(x + e1.x) + lane);
        float4 x2 = __ldg((const float4*)(x + e2.x) + lane);
        float4 x3 = __ldg((const float4*)(x + e3.x) + lane);
        float v0 = __int_as_float(e0.y), v1 = __int_as_float(e1.y);
        float v2 = __int_as_float(e2.y), v3 = __int_as_float(e3.y);
        acc.x  += v0 * x0.x; acc.y  += v0 * x0.y; acc.z  += v0 * x0.z; acc.w  += v0 * x0.w;
        acc2.x += v1 * x1.x; acc2.y += v1 * x1.y; acc2.z += v1 * x1.z; acc2.w += v1 * x1.w;
        acc.x  += v2 * x2.x; acc.y  += v2 * x2.y; acc.z  += v2 * x2.z; acc.w  += v2 * x2.w;
        acc2.x += v3 * x3.x; acc2.y += v3 * x3.y; acc2.z += v3 * x3.z; acc2.w += v3 * x3.w;
    }
    for (; k < e; k++) {
        int2 ed = __ldg(&g_edges[k]);
        float4 xv = __ldg((const float4*)(x + ed.x) + lane);
        float v = __int_as_float(ed.y);
        acc.x += v * xv.x; acc.y += v * xv.y; acc.z += v * xv.z; acc.w += v * xv.w;
    }
    acc.x += acc2.x; acc.y += acc2.y; acc.z += acc2.z; acc.w += acc2.w;
    return acc;
}

__global__ void __launch_bounds__(256) spmm_kernel(
    const float* __restrict__ x, float* __restrict__ y) {
    const int r = (blockIdx.x * blockDim.x + threadIdx.x) >> 5;
    if (r >= N_NODES) return;
    const int lane = threadIdx.x & 31;
    float4 acc = spmm_row(x, r, lane);
    if (lane < NF4)
        ((float4*)(y + (size_t)r * EMB))[lane] = acc;
}

// ---------------- layer-3 SpMM fused with normalize + weighted sum ----------------
__device__ __forceinline__ float dot4(float4 p) {
    return p.x * p.x + p.y * p.y + p.z * p.z + p.w * p.w;
}

__global__ void __launch_bounds__(256) spmm_final_kernel(
    const float* __restrict__ x2in, const float* __restrict__ emb,
    const float* __restrict__ a, float* __restrict__ out) {
    const int r = (blockIdx.x * blockDim.x + threadIdx.x) >> 5;
    if (r >= N_NODES) return;
    const int lane = threadIdx.x & 31;

    float4 v3 = spmm_row(x2in, r, lane);   // layer 3 row, in registers (zero for lane>=NF4)

    const float4 zero = make_float4(0.f, 0.f, 0.f, 0.f);
    float4 v0 = zero, v1 = zero, v2 = zero;
    if (lane < NF4) {
        v0 = __ldg((const float4*)(emb  + (size_t)r * EMB) + lane);
        v1 = __ldg((const float4*)(g_x1 + (size_t)r * EMB) + lane);
        v2 = __ldg((const float4*)(g_x2 + (size_t)r * EMB) + lane);
    }

    float sq[4];
    sq[0] = dot4(v0); sq[1] = dot4(v1); sq[2] = dot4(v2); sq[3] = dot4(v3);

    #pragma unroll
    for (int off = 16; off > 0; off >>= 1) {
        #pragma unroll
        for (int l = 0; l < 4; l++)
            sq[l] += __shfl_xor_sync(0xFFFFFFFFu, sq[l], off);
    }

    if (lane < NF4) {
        float w0 = __ldg(&a[0]) / fmaxf(sqrtf(sq[0]), 1e-12f);
        float w1 = __ldg(&a[1]) / fmaxf(sqrtf(sq[1]), 1e-12f);
        float w2 = __ldg(&a[2]) / fmaxf(sqrtf(sq[2]), 1e-12f);
        float w3 = __ldg(&a[3]) / fmaxf(sqrtf(sq[3]), 1e-12f);
        float4 res;
        res.x = w0 * v0.x + w1 * v1.x + w2 * v2.x + w3 * v3.x;
        res.y = w0 * v0.y + w1 * v1.y + w2 * v2.y + w3 * v3.y;
        res.z = w0 * v0.z + w1 * v1.z + w2 * v2.z + w3 * v3.z;
        res.w = w0 * v0.w + w1 * v1.w + w2 * v2.w + w3 * v3.w;
        ((float4*)(out + (size_t)r * EMB))[lane] = res;
    }
}

extern "C" void kernel_launch(void* const* d_in, const int* in_sizes, int n_in,
                              void* d_out, int out_size) {
    const int*   adj_row = (const int*)d_in[0];
    const int*   adj_col = (const int*)d_in[1];
    const float* adj_val = (const float*)d_in[2];
    const float* emb     = (const float*)d_in[3];
    const float* a       = (const float*)d_in[4];
    float*       out     = (float*)d_out;

    float* x1;  cudaGetSymbolAddress((void**)&x1, g_x1);
    float* x2;  cudaGetSymbolAddress((void**)&x2, g_x2);
    int*   cur; cudaGetSymbolAddress((void**)&cur, g_cursor);
    int*   flg; cudaGetSymbolAddress((void**)&flg, g_flag);

    // CSR build
    cudaMemsetAsync(cur, 0, N_NODES * sizeof(int), 0);
    cudaMemsetAsync(flg, 0, SCAN_NB * sizeof(int), 0);
    hist_kernel<<<(N_EDGES + 255) / 256, 256>>>(adj_row);
    scan_lookback_kernel<<<SCAN_NB, SCAN_B>>>();
    scatter_kernel<<<(N_EDGES + 255) / 256, 256>>>(adj_row, adj_col, adj_val);

    // SpMM layers (warp per row); layer 3 fused with normalize+sum
    const int SPMM_BLOCKS = (N_NODES * 32 + 255) / 256;
    spmm_kernel<<<SPMM_BLOCKS, 256>>>(emb, x1);
    spmm_kernel<<<SPMM_BLOCKS, 256>>>(x1,  x2);
    spmm_final_kernel<<<SPMM_BLOCKS, 256>>>(x2, emb, a, out);
}